// round 8
// baseline (speedup 1.0000x reference)
#include <cuda_runtime.h>
#include <cuda_bf16.h>
#include <cstdint>

#define B_  8
#define C_  64
#define CO_ 64
#define H_  128
#define W_  128
#define HW_ (H_*W_)

// Scratch (device globals — no allocation allowed)
__device__ __align__(16)   float         g_off[B_*4*HW_];     // offsets o[b][4][h][w]
__device__ __align__(1024) __nv_bfloat16 g_wbf[9*2*4096];     // per tap: [hi 8KB][lo 8KB], SW128 [o][c]
__device__ __align__(16)   float         g_xt[B_*H_*W_*C_];   // x transposed: [b][y][x][c]  (32 MB)

__constant__ int c_dysel[9] = {0,1,4,0,1,2,4,4,3};   // 0=t 1=b 2=l 3=r 4=zero
__constant__ int c_dxsel[9] = {4,0,1,4,2,2,4,3,3};

// ---------------------------------------------------------------- PTX helpers (all sm_80+ baseline)
#define CP_ASYNC16(saddr, gptr) \
    asm volatile("cp.async.cg.shared.global [%0], [%1], 16;" :: "r"(saddr), "l"(gptr) : "memory")
#define CP_COMMIT()  asm volatile("cp.async.commit_group;" ::: "memory")
#define CP_WAIT(n)   asm volatile("cp.async.wait_group %0;" :: "n"(n) : "memory")

#define LDSM_X4(r0,r1,r2,r3, addr) \
    asm volatile("ldmatrix.sync.aligned.m8n8.x4.shared.b16 {%0,%1,%2,%3}, [%4];" \
                 : "=r"(r0), "=r"(r1), "=r"(r2), "=r"(r3) : "r"(addr))

// res = bf16x2 {lo half: bf16(lo), hi half: bf16(hi)}
#define CVT2(res, lo, hi) \
    asm("cvt.rn.bf16x2.f32 %0, %1, %2;" : "=r"(res) : "f"(hi), "f"(lo))

__device__ __forceinline__ void mma16816(float* d, const uint32_t* a, const uint32_t* b) {
    asm volatile("mma.sync.aligned.m16n8k16.row.col.f32.bf16.bf16.f32 "
        "{%0,%1,%2,%3}, {%4,%5,%6,%7}, {%8,%9}, {%0,%1,%2,%3};"
        : "+f"(d[0]), "+f"(d[1]), "+f"(d[2]), "+f"(d[3])
        : "r"(a[0]), "r"(a[1]), "r"(a[2]), "r"(a[3]), "r"(b[0]), "r"(b[1]));
}

__device__ __forceinline__ uint32_t s2u(const void* p) {
    uint32_t a;
    asm("{ .reg .u64 t; cvta.to.shared.u64 t, %1; cvt.u32.u64 %0, t; }" : "=r"(a) : "l"(p));
    return a;
}

__host__ __device__ __forceinline__ unsigned sw128(unsigned x) { return x ^ ((x >> 3) & 0x70); }

// ---------------------------------------------------------------- x transpose: [b][c][y][x] -> [b][y][x][c]
__global__ void xT_kernel(const float* __restrict__ x) {
    int b = blockIdx.x >> 7;
    int y = blockIdx.x & 127;
    int t = threadIdx.x;               // t = x coordinate (128 threads)
    const float* src = x + ((size_t)b*C_)*HW_ + y*W_ + t;
    float* dst = g_xt + (((size_t)(b*H_ + y))*W_ + t)*C_;
    #pragma unroll 2
    for (int half = 0; half < 2; half++) {
        float v[32];
        #pragma unroll
        for (int c = 0; c < 32; c++) v[c] = src[(size_t)(half*32 + c)*HW_];
        float4* d4 = (float4*)(dst + half*32);
        #pragma unroll
        for (int i = 0; i < 8; i++)
            d4[i] = make_float4(v[4*i], v[4*i+1], v[4*i+2], v[4*i+3]);
    }
}

// ---------------------------------------------------------------- weight prep: bf16 hi/lo split, SW128 [o][c]
__global__ void wprep_kernel(const float* __restrict__ weight) {
    int idx = blockIdx.x*256 + threadIdx.x;       // 9*4096
    if (idx < 9*4096) {
        int k = idx >> 12;
        int r = idx & 4095;
        int o = r >> 6;
        int c = r & 63;
        float v = weight[(o*C_ + c)*9 + k];
        __nv_bfloat16 hb = __float2bfloat16(v);
        __nv_bfloat16 lb = __float2bfloat16(v - __bfloat162float(hb));
        unsigned so = sw128((unsigned)(o*128 + c*2));
        char* base = (char*)g_wbf + k*16384;
        *(__nv_bfloat16*)(base + so)        = hb;
        *(__nv_bfloat16*)(base + 8192 + so) = lb;
    }
}

// ---------------------------------------------------------------- offset conv (4 out ch)
__global__ void offset_kernel(const float* __restrict__ x,
                              const float* __restrict__ ow,
                              const float* __restrict__ ob) {
    __shared__ float ws[4*C_*9];
    int b = blockIdx.x >> 7;
    int h = blockIdx.x & 127;
    int t = threadIdx.x;
    for (int i = t; i < 4*C_*9; i += 128) ws[i] = ow[i];
    __syncthreads();

    float a0 = ob[0], a1 = ob[1], a2 = ob[2], a3 = ob[3];
    const float* xb = x + (size_t)b*C_*HW_;
    int w = t;
    for (int c = 0; c < C_; c++) {
        const float* xp = xb + c*HW_;
        #pragma unroll
        for (int i = 0; i < 3; i++) {
            int y = h - 1 + i;
            if ((unsigned)y >= (unsigned)H_) continue;
            #pragma unroll
            for (int j = 0; j < 3; j++) {
                int xx = w - 1 + j;
                if ((unsigned)xx >= (unsigned)W_) continue;
                float v = xp[y*W_ + xx];
                int kk = i*3 + j;
                a0 += v * ws[(0*C_ + c)*9 + kk];
                a1 += v * ws[(1*C_ + c)*9 + kk];
                a2 += v * ws[(2*C_ + c)*9 + kk];
                a3 += v * ws[(3*C_ + c)*9 + kk];
            }
        }
    }
    int base = ((b*4 + 0)*H_ + h)*W_ + w;
    g_off[base]          = a0;
    g_off[base +   HW_]  = a1;
    g_off[base + 2*HW_]  = a2;
    g_off[base + 3*HW_]  = a3;
}

// ---------------------------------------------------------------- bilinear setup (verified R5)
__device__ __forceinline__ float selo(int s, float t, float b, float l, float r) {
    switch (s) {
        case 0: return t;
        case 1: return b;
        case 2: return l;
        case 3: return r;
        default: return 0.f;
    }
}
__device__ __forceinline__ void phaseA_reg(int k, int h, int w,
                                           float o_t, float o_b, float o_l, float o_r,
                                           int& base, float& q00, float& q01,
                                           float& q10, float& q11) {
    int ki = k / 3, kj = k % 3;
    float dy = selo(c_dysel[k], o_t, o_b, o_l, o_r);
    float dx = selo(c_dxsel[k], o_t, o_b, o_l, o_r);
    float py = (float)(h - 1 + ki) + dy;
    float px = (float)(w - 1 + kj) + dx;
    float yf = floorf(py), xf = floorf(px);
    float ly = py - yf,   lx = px - xf;
    int y0 = (int)yf, x0 = (int)xf;
    int yb = min(max(y0, 0), H_-2);
    int xb = min(max(x0, 0), W_-2);
    float cy0 = (y0 == yb) ? (1.f - ly) : ((y0 == -1)   ? ly        : 0.f);
    float cy1 = (y0 == yb) ? ly         : ((y0 == H_-1) ? (1.f - ly) : 0.f);
    float cx0 = (x0 == xb) ? (1.f - lx) : ((x0 == -1)   ? lx        : 0.f);
    float cx1 = (x0 == xb) ? lx         : ((x0 == W_-1) ? (1.f - lx) : 0.f);
    q00 = cy0*cx0; q01 = cy0*cx1; q10 = cy1*cx0; q11 = cy1*cx1;
    base = yb*W_ + xb;
}

// ---------------------------------------------------------------- main mma.sync kernel
// smem bytes: Wbuf0 16K | Wbuf1 16K | Sh 16K | Sl 16K = 64 KB -> 2 CTAs/SM
#define SM_W0    0
#define SM_SH    32768
#define SM_SL    49152
#define SM_BYTES 65536

__global__ void __launch_bounds__(256, 2)
main_kernel(const float* __restrict__ x, float* __restrict__ out) {
    extern __shared__ char smem[];
    uint32_t sb = s2u(smem);
    char* ShP = smem + SM_SH;
    char* SlP = smem + SM_SL;

    int b = blockIdx.x >> 7;
    int h = blockIdx.x & 127;
    int t = threadIdx.x;
    int lane = t & 31;
    int wid  = t >> 5;
    int w    = t & 127;      // gather w position
    int cb   = t >> 7;       // gather channel half (0: c 0-31, 1: c 32-63)

    // warp tile: o range [otile, otile+16), w range [w0, w0+64)
    int otile = (wid & 3) * 16;
    int w0    = (wid >> 2) * 64;

    // ldmatrix per-lane row/offset precompute
    unsigned a_row  = otile + (lane & 15);                            // weights [o][c]
    unsigned a_koff = ((unsigned)lane >> 4) * 16;
    unsigned b_row  = w0 + (lane & 7) + (((unsigned)lane >> 4) & 1) * 8;  // samples [w][c]
    unsigned b_koff = (((unsigned)lane >> 3) & 1) * 16;

    // ---- cp.async tap-0 weights into Wbuf0 ----
    {
        const char* src = (const char*)g_wbf;
        #pragma unroll
        for (int i = 0; i < 4; i++) {
            int ch = i*256 + t;
            CP_ASYNC16(sb + SM_W0 + ch*16, src + ch*16);
        }
        CP_COMMIT();
    }

    float o_t, o_b, o_l, o_r;
    {
        int ob_ = ((b*4 + 0)*H_ + h)*W_ + w;
        o_t = g_off[ob_];
        o_b = g_off[ob_ +   HW_];
        o_l = g_off[ob_ + 2*HW_];
        o_r = g_off[ob_ + 3*HW_];
    }

    // channel-last image base for this (b); thread's channel base
    const float* xtb = g_xt + ((size_t)b*HW_)*C_ + cb*32;

    float acc[8][4];
    #pragma unroll
    for (int ni = 0; ni < 8; ni++)
        #pragma unroll
        for (int j = 0; j < 4; j++) acc[ni][j] = 0.f;

    #pragma unroll 1
    for (int k = 0; k < 9; k++) {
        __syncthreads();      // S tiles free (prev tap's MMA done); W buf (k+1)&1 free

        // prefetch weights for tap k+1
        if (k < 8) {
            const char* src = (const char*)g_wbf + (k+1)*16384;
            uint32_t dst = sb + SM_W0 + ((k+1)&1)*16384;
            #pragma unroll
            for (int i = 0; i < 4; i++) {
                int ch = i*256 + t;
                CP_ASYNC16(dst + ch*16, src + ch*16);
            }
            CP_COMMIT();
        }

        // ---- gather: 8 chunks x 4 corners, float4 channel-contiguous loads ----
        {
            int gbase; float q00, q01, q10, q11;
            phaseA_reg(k, h, w, o_t, o_b, o_l, o_r, gbase, q00, q01, q10, q11);
            const float* gp = xtb + (size_t)gbase*C_;
            #pragma unroll
            for (int j = 0; j < 8; j++) {
                const float* p = gp + 4*j;
                float4 va = *(const float4*)(p);
                float4 vb = *(const float4*)(p + C_);
                float4 vc = *(const float4*)(p + C_*W_);
                float4 vd = *(const float4*)(p + C_*W_ + C_);
                float v0 = q00*va.x + q01*vb.x + q10*vc.x + q11*vd.x;
                float v1 = q00*va.y + q01*vb.y + q10*vc.y + q11*vd.y;
                float v2 = q00*va.z + q01*vb.z + q10*vc.z + q11*vd.z;
                float v3 = q00*va.w + q01*vb.w + q10*vc.w + q11*vd.w;

                uint32_t hp0, hp1, lp0, lp1;
                CVT2(hp0, v0, v1);
                CVT2(hp1, v2, v3);
                float vh0 = __uint_as_float(hp0 << 16);
                float vh1 = __uint_as_float(hp0 & 0xFFFF0000u);
                float vh2 = __uint_as_float(hp1 << 16);
                float vh3 = __uint_as_float(hp1 & 0xFFFF0000u);
                CVT2(lp0, v0 - vh0, v1 - vh1);
                CVT2(lp1, v2 - vh2, v3 - vh3);

                unsigned off = sw128((unsigned)(w*128 + (cb*32 + 4*j)*2));
                *(uint2*)(ShP + off) = make_uint2(hp0, hp1);
                *(uint2*)(SlP + off) = make_uint2(lp0, lp1);
            }
        }

        if (k < 8) { CP_WAIT(1); } else { CP_WAIT(0); }   // W(k) landed
        __syncthreads();                                  // S + W(k) visible CTA-wide

        // ---- MMA phase: 4 K-chunks x (Wh*Sh + Wl*Sh + Wh*Sl) ----
        uint32_t wb = sb + SM_W0 + (k&1)*16384;
        #pragma unroll
        for (int ks = 0; ks < 4; ks++) {
            unsigned aoff = sw128(a_row*128 + ks*32 + a_koff);
            uint32_t ah[4], al[4];
            LDSM_X4(ah[0], ah[1], ah[2], ah[3], wb + aoff);
            LDSM_X4(al[0], al[1], al[2], al[3], wb + 8192 + aoff);

            uint32_t bh[16];
            #pragma unroll
            for (int j = 0; j < 4; j++) {
                unsigned boff = sw128((b_row + j*16)*128 + ks*32 + b_koff);
                LDSM_X4(bh[4*j], bh[4*j+1], bh[4*j+2], bh[4*j+3], sb + SM_SH + boff);
            }
            #pragma unroll
            for (int ni = 0; ni < 8; ni++) mma16816(acc[ni], ah, &bh[ni*2]);
            #pragma unroll
            for (int ni = 0; ni < 8; ni++) mma16816(acc[ni], al, &bh[ni*2]);

            uint32_t bl[16];
            #pragma unroll
            for (int j = 0; j < 4; j++) {
                unsigned boff = sw128((b_row + j*16)*128 + ks*32 + b_koff);
                LDSM_X4(bl[4*j], bl[4*j+1], bl[4*j+2], bl[4*j+3], sb + SM_SL + boff);
            }
            #pragma unroll
            for (int ni = 0; ni < 8; ni++) mma16816(acc[ni], ah, &bl[ni*2]);
        }
    }

    // ---- epilogue: d[o][w] fragments -> out[b][o][h][w] (STG.64 over w pairs) ----
    {
        int o_r = otile + (lane >> 2);
        int w_c = w0 + (lane & 3) * 2;
        float* op = out + (((size_t)b*CO_ + o_r)*H_ + h)*W_ + w_c;
        #pragma unroll
        for (int ni = 0; ni < 8; ni++) {
            *(float2*)(op + ni*8)              = make_float2(acc[ni][0], acc[ni][1]);
            *(float2*)(op + 8*HW_ + ni*8)      = make_float2(acc[ni][2], acc[ni][3]);
        }
    }
}

// ---------------------------------------------------------------- launch
extern "C" void kernel_launch(void* const* d_in, const int* in_sizes, int n_in,
                              void* d_out, int out_size) {
    const float* x  = (const float*)d_in[0];   // (8,64,128,128)
    const float* ow = (const float*)d_in[1];   // (4,64,3,3)
    const float* ob = (const float*)d_in[2];   // (4,)
    const float* wt = (const float*)d_in[3];   // (64,64,3,3)
    float* out = (float*)d_out;                // (8,64,128,128)

    cudaFuncSetAttribute(main_kernel, cudaFuncAttributeMaxDynamicSharedMemorySize, SM_BYTES);

    xT_kernel<<<B_*H_, 128>>>(x);
    wprep_kernel<<<(9*4096 + 255)/256, 256>>>(wt);
    offset_kernel<<<B_*H_, 128>>>(x, ow, ob);
    main_kernel<<<B_*H_, 256, SM_BYTES>>>(x, out);
}

// round 9
// speedup vs baseline: 1.5387x; 1.5387x over previous
#include <cuda_runtime.h>
#include <cuda_bf16.h>
#include <cstdint>

#define B_  8
#define C_  64
#define CO_ 64
#define H_  128
#define W_  128
#define HW_ (H_*W_)

// Scratch (device globals — no allocation allowed)
__device__ __align__(16)   float         g_off[B_*4*HW_];     // offsets o[b][4][h][w]
__device__ __align__(1024) __nv_bfloat16 g_wbf[9*2*4096];     // per tap: [hi 8KB][lo 8KB], SW128 [o][c]

__constant__ int c_dysel[9] = {0,1,4,0,1,2,4,4,3};   // 0=t 1=b 2=l 3=r 4=zero
__constant__ int c_dxsel[9] = {4,0,1,4,2,2,4,3,3};

// ---------------------------------------------------------------- PTX helpers (all sm_80+ baseline)
#define CP_ASYNC16(saddr, gptr) \
    asm volatile("cp.async.cg.shared.global [%0], [%1], 16;" :: "r"(saddr), "l"(gptr) : "memory")
#define CP_COMMIT()  asm volatile("cp.async.commit_group;" ::: "memory")
#define CP_WAIT(n)   asm volatile("cp.async.wait_group %0;" :: "n"(n) : "memory")

#define LDSM_X4(r0,r1,r2,r3, addr) \
    asm volatile("ldmatrix.sync.aligned.m8n8.x4.shared.b16 {%0,%1,%2,%3}, [%4];" \
                 : "=r"(r0), "=r"(r1), "=r"(r2), "=r"(r3) : "r"(addr))

// res = bf16x2 {lo half: bf16(lo), hi half: bf16(hi)}
#define CVT2(res, lo, hi) \
    asm("cvt.rn.bf16x2.f32 %0, %1, %2;" : "=r"(res) : "f"(hi), "f"(lo))

__device__ __forceinline__ void mma16816(float* d, const uint32_t* a, const uint32_t* b) {
    asm volatile("mma.sync.aligned.m16n8k16.row.col.f32.bf16.bf16.f32 "
        "{%0,%1,%2,%3}, {%4,%5,%6,%7}, {%8,%9}, {%0,%1,%2,%3};"
        : "+f"(d[0]), "+f"(d[1]), "+f"(d[2]), "+f"(d[3])
        : "r"(a[0]), "r"(a[1]), "r"(a[2]), "r"(a[3]), "r"(b[0]), "r"(b[1]));
}

__device__ __forceinline__ uint32_t s2u(const void* p) {
    uint32_t a;
    asm("{ .reg .u64 t; cvta.to.shared.u64 t, %1; cvt.u32.u64 %0, t; }" : "=r"(a) : "l"(p));
    return a;
}

__host__ __device__ __forceinline__ unsigned sw128(unsigned x) { return x ^ ((x >> 3) & 0x70); }

// ---------------------------------------------------------------- weight prep: bf16 hi/lo split, SW128 [o][c]
__global__ void wprep_kernel(const float* __restrict__ weight) {
    int idx = blockIdx.x*256 + threadIdx.x;       // 9*4096
    if (idx < 9*4096) {
        int k = idx >> 12;
        int r = idx & 4095;
        int o = r >> 6;
        int c = r & 63;
        float v = weight[(o*C_ + c)*9 + k];
        __nv_bfloat16 hb = __float2bfloat16(v);
        __nv_bfloat16 lb = __float2bfloat16(v - __bfloat162float(hb));
        unsigned so = sw128((unsigned)(o*128 + c*2));
        char* base = (char*)g_wbf + k*16384;
        *(__nv_bfloat16*)(base + so)        = hb;
        *(__nv_bfloat16*)(base + 8192 + so) = lb;
    }
}

// ---------------------------------------------------------------- offset conv (4 out ch)
__global__ void offset_kernel(const float* __restrict__ x,
                              const float* __restrict__ ow,
                              const float* __restrict__ ob) {
    __shared__ float ws[4*C_*9];
    int b = blockIdx.x >> 7;
    int h = blockIdx.x & 127;
    int t = threadIdx.x;
    for (int i = t; i < 4*C_*9; i += 128) ws[i] = ow[i];
    __syncthreads();

    float a0 = ob[0], a1 = ob[1], a2 = ob[2], a3 = ob[3];
    const float* xb = x + (size_t)b*C_*HW_;
    int w = t;
    for (int c = 0; c < C_; c++) {
        const float* xp = xb + c*HW_;
        #pragma unroll
        for (int i = 0; i < 3; i++) {
            int y = h - 1 + i;
            if ((unsigned)y >= (unsigned)H_) continue;
            #pragma unroll
            for (int j = 0; j < 3; j++) {
                int xx = w - 1 + j;
                if ((unsigned)xx >= (unsigned)W_) continue;
                float v = xp[y*W_ + xx];
                int kk = i*3 + j;
                a0 += v * ws[(0*C_ + c)*9 + kk];
                a1 += v * ws[(1*C_ + c)*9 + kk];
                a2 += v * ws[(2*C_ + c)*9 + kk];
                a3 += v * ws[(3*C_ + c)*9 + kk];
            }
        }
    }
    int base = ((b*4 + 0)*H_ + h)*W_ + w;
    g_off[base]          = a0;
    g_off[base +   HW_]  = a1;
    g_off[base + 2*HW_]  = a2;
    g_off[base + 3*HW_]  = a3;
}

// ---------------------------------------------------------------- bilinear setup (verified R5/R7)
__device__ __forceinline__ float selo(int s, float t, float b, float l, float r) {
    switch (s) {
        case 0: return t;
        case 1: return b;
        case 2: return l;
        case 3: return r;
        default: return 0.f;
    }
}
__device__ __forceinline__ void phaseA_reg(int k, int h, int w,
                                           float o_t, float o_b, float o_l, float o_r,
                                           int& base, float& q00, float& q01,
                                           float& q10, float& q11) {
    int ki = k / 3, kj = k % 3;
    float dy = selo(c_dysel[k], o_t, o_b, o_l, o_r);
    float dx = selo(c_dxsel[k], o_t, o_b, o_l, o_r);
    float py = (float)(h - 1 + ki) + dy;
    float px = (float)(w - 1 + kj) + dx;
    float yf = floorf(py), xf = floorf(px);
    float ly = py - yf,   lx = px - xf;
    int y0 = (int)yf, x0 = (int)xf;
    int yb = min(max(y0, 0), H_-2);
    int xb = min(max(x0, 0), W_-2);
    float cy0 = (y0 == yb) ? (1.f - ly) : ((y0 == -1)   ? ly        : 0.f);
    float cy1 = (y0 == yb) ? ly         : ((y0 == H_-1) ? (1.f - ly) : 0.f);
    float cx0 = (x0 == xb) ? (1.f - lx) : ((x0 == -1)   ? lx        : 0.f);
    float cx1 = (x0 == xb) ? lx         : ((x0 == W_-1) ? (1.f - lx) : 0.f);
    q00 = cy0*cx0; q01 = cy0*cx1; q10 = cy1*cx0; q11 = cy1*cx1;
    base = yb*W_ + xb;
}

// ---------------------------------------------------------------- main mma.sync kernel
// 128-thread CTAs, one per (b, h, whalf): 64 w x 64 o tile.
// smem: Wbuf0 16K | Wbuf1 16K | Sh 8K | Sl 8K = 48 KB -> 4 CTAs/SM
#define SM_W0    0
#define SM_SH    32768
#define SM_SL    40960
#define SM_BYTES 49152

__global__ void __launch_bounds__(128, 4)
main_kernel(const float* __restrict__ x, float* __restrict__ out) {
    extern __shared__ char smem[];
    uint32_t sb = s2u(smem);
    char* ShP = smem + SM_SH;
    char* SlP = smem + SM_SL;

    int b     = blockIdx.x >> 8;
    int h     = (blockIdx.x >> 1) & 127;
    int whalf = blockIdx.x & 1;

    int t = threadIdx.x;
    int lane = t & 31;
    int wid  = t >> 5;           // 4 warps
    int w    = t & 63;           // gather w position (within half)
    int cb   = t >> 6;           // gather channel half (0: c 0-31, 1: c 32-63)
    int wg   = whalf*64 + w;     // global w

    // warp tile: o range [otile, otile+16), w range [0, 64)
    int otile = wid * 16;

    // ldmatrix per-lane row/offset precompute
    unsigned a_row  = otile + (lane & 15);                                // weights [o][c]
    unsigned a_koff = ((unsigned)lane >> 4) * 16;
    unsigned b_row  = (lane & 7) + (((unsigned)lane >> 4) & 1) * 8;       // samples [w][c]
    unsigned b_koff = (((unsigned)lane >> 3) & 1) * 16;

    // ---- cp.async tap-0 weights into Wbuf0 ----
    {
        const char* src = (const char*)g_wbf;
        #pragma unroll
        for (int i = 0; i < 8; i++) {
            int ch = i*128 + t;
            CP_ASYNC16(sb + SM_W0 + ch*16, src + ch*16);
        }
        CP_COMMIT();
    }

    const float* xb = x + (size_t)b*C_*HW_;
    float o_t, o_b, o_l, o_r;
    {
        int ob_ = ((b*4 + 0)*H_ + h)*W_ + wg;
        o_t = g_off[ob_];
        o_b = g_off[ob_ +   HW_];
        o_l = g_off[ob_ + 2*HW_];
        o_r = g_off[ob_ + 3*HW_];
    }

    float acc[8][4];
    #pragma unroll
    for (int ni = 0; ni < 8; ni++)
        #pragma unroll
        for (int j = 0; j < 4; j++) acc[ni][j] = 0.f;

    #pragma unroll 1
    for (int k = 0; k < 9; k++) {
        __syncthreads();      // S tiles free (prev tap's MMA done); W buf (k+1)&1 free

        // prefetch weights for tap k+1
        if (k < 8) {
            const char* src = (const char*)g_wbf + (k+1)*16384;
            uint32_t dst = sb + SM_W0 + ((k+1)&1)*16384;
            #pragma unroll
            for (int i = 0; i < 8; i++) {
                int ch = i*128 + t;
                CP_ASYNC16(dst + ch*16, src + ch*16);
            }
            CP_COMMIT();
        }

        // ---- gather + bf16 hi/lo split into Sh/Sl (dist-4 LDG ring, pair-packed STS.32) ----
        {
            int gbase; float q00, q01, q10, q11;
            phaseA_reg(k, h, wg, o_t, o_b, o_l, o_r, gbase, q00, q01, q10, q11);
            const float* gp = xb + (size_t)(cb*32)*HW_ + gbase;
            float pr[16];
            float vE = 0.f, lE = 0.f;
            #pragma unroll
            for (int i = 0; i < 36; i++) {
                int slot = (i & 3) * 4;
                if (i >= 4) {
                    int ii = i - 4;                 // channel index within half
                    float v = q00*pr[slot] + q01*pr[slot+1]
                            + q10*pr[slot+2] + q11*pr[slot+3];
                    float vh = __bfloat162float(__float2bfloat16(v));
                    float vl = v - vh;
                    if ((ii & 1) == 0) { vE = v; lE = vl; }
                    else {
                        int c0 = cb*32 + ii - 1;    // even channel of the pair
                        uint32_t hp, lp;
                        CVT2(hp, vE, v);
                        CVT2(lp, lE, vl);
                        unsigned off = sw128((unsigned)(w*128 + c0*2));
                        *(uint32_t*)(ShP + off) = hp;
                        *(uint32_t*)(SlP + off) = lp;
                    }
                }
                if (i < 32) {
                    const float* p = gp + (size_t)i*HW_;
                    pr[slot]   = p[0];
                    pr[slot+1] = p[1];
                    pr[slot+2] = p[W_];
                    pr[slot+3] = p[W_+1];
                }
            }
        }

        if (k < 8) { CP_WAIT(1); } else { CP_WAIT(0); }   // W(k) landed
        __syncthreads();                                  // S + W(k) visible CTA-wide

        // ---- MMA phase: 4 K-chunks x (Wh*Sh + Wl*Sh + Wh*Sl) ----
        uint32_t wb = sb + SM_W0 + (k&1)*16384;
        #pragma unroll
        for (int ks = 0; ks < 4; ks++) {
            unsigned aoff = sw128(a_row*128 + ks*32 + a_koff);
            uint32_t ah[4], al[4];
            LDSM_X4(ah[0], ah[1], ah[2], ah[3], wb + aoff);
            LDSM_X4(al[0], al[1], al[2], al[3], wb + 8192 + aoff);

            uint32_t bh[16];
            #pragma unroll
            for (int j = 0; j < 4; j++) {
                unsigned boff = sw128((b_row + j*16)*128 + ks*32 + b_koff);
                LDSM_X4(bh[4*j], bh[4*j+1], bh[4*j+2], bh[4*j+3], sb + SM_SH + boff);
            }
            #pragma unroll
            for (int ni = 0; ni < 8; ni++) mma16816(acc[ni], ah, &bh[ni*2]);
            #pragma unroll
            for (int ni = 0; ni < 8; ni++) mma16816(acc[ni], al, &bh[ni*2]);

            uint32_t bl[16];
            #pragma unroll
            for (int j = 0; j < 4; j++) {
                unsigned boff = sw128((b_row + j*16)*128 + ks*32 + b_koff);
                LDSM_X4(bl[4*j], bl[4*j+1], bl[4*j+2], bl[4*j+3], sb + SM_SL + boff);
            }
            #pragma unroll
            for (int ni = 0; ni < 8; ni++) mma16816(acc[ni], ah, &bl[ni*2]);
        }
    }

    // ---- epilogue: d[o][w] fragments -> out[b][o][h][w] (STG.64 over w pairs) ----
    {
        int o_r = otile + (lane >> 2);
        int w_c = whalf*64 + (lane & 3) * 2;
        float* op = out + (((size_t)b*CO_ + o_r)*H_ + h)*W_ + w_c;
        #pragma unroll
        for (int ni = 0; ni < 8; ni++) {
            *(float2*)(op + ni*8)         = make_float2(acc[ni][0], acc[ni][1]);
            *(float2*)(op + 8*HW_ + ni*8) = make_float2(acc[ni][2], acc[ni][3]);
        }
    }
}

// ---------------------------------------------------------------- launch
extern "C" void kernel_launch(void* const* d_in, const int* in_sizes, int n_in,
                              void* d_out, int out_size) {
    const float* x  = (const float*)d_in[0];   // (8,64,128,128)
    const float* ow = (const float*)d_in[1];   // (4,64,3,3)
    const float* ob = (const float*)d_in[2];   // (4,)
    const float* wt = (const float*)d_in[3];   // (64,64,3,3)
    float* out = (float*)d_out;                // (8,64,128,128)

    cudaFuncSetAttribute(main_kernel, cudaFuncAttributeMaxDynamicSharedMemorySize, SM_BYTES);

    wprep_kernel<<<(9*4096 + 255)/256, 256>>>(wt);
    offset_kernel<<<B_*H_, 128>>>(x, ow, ob);
    main_kernel<<<B_*H_*2, 128, SM_BYTES>>>(x, out);
}